// round 5
// baseline (speedup 1.0000x reference)
#include <cuda_runtime.h>
#include <math.h>

// Problem dims (fixed by the reference)
#define NT    16384          // N*T rows
#define WDIM  512            // feature dim
#define KC    2048           // codebook size
#define NB    16             // N
#define TB    1024           // T

#define MU_F   0.99f
#define OMM_F  ((float)(1.0 - 0.99))   // exact JAX constant: double 1-0.99 rounded to f32

// Output layout (tuple flattened, float32):
// x_l[16384] | x_d[8388608] | commit | fit | prenorm | entropy | dk | k_new[1048576] | k_sum_new[1048576] | k_elem_new[2048]
#define O_XL     0
#define O_XD     16384
#define O_SCAL   8404992
#define O_KNEW   8404997
#define O_KSUM   9453573
#define O_KELEM  10502149

// -------- scratch (static device globals; no runtime allocation) --------
__device__ float  g_xf[(size_t)NT * WDIM];      // 32 MB transposed input
__device__ float  g_rownorm[NT];
__device__ float  g_knorm[KC];
__device__ int    g_xl[NT];
__device__ float  g_ksum_acc[(size_t)KC * WDIM];
__device__ float  g_kelem_acc[KC];
__device__ double g_red[8];                      // 0 sum, 1 sumsq, 2 fit, 3 commit, 4 dk
// permutation machinery (jax.random.permutation(key(42), xf) reproduction)
__device__ unsigned int g_sk1[NT];
__device__ unsigned int g_sk2[NT];
__device__ int    g_v1[NT];
__device__ int    g_ind[NT];

// -------- f32x2 packed-FMA helpers (Blackwell dual fp32) --------
__device__ __forceinline__ unsigned long long ffma2(unsigned long long a,
                                                    unsigned long long b,
                                                    unsigned long long c) {
    unsigned long long d;
    asm("fma.rn.f32x2 %0, %1, %2, %3;" : "=l"(d) : "l"(a), "l"(b), "l"(c));
    return d;
}
__device__ __forceinline__ unsigned long long pack2(float lo, float hi) {
    unsigned long long d;
    asm("mov.b64 %0, {%1, %2};" : "=l"(d)
        : "r"(__float_as_uint(lo)), "r"(__float_as_uint(hi)));
    return d;
}
__device__ __forceinline__ float2 unpack2(unsigned long long v) {
    unsigned int lo, hi;
    asm("mov.b64 {%0, %1}, %2;" : "=r"(lo), "=r"(hi) : "l"(v));
    return make_float2(__uint_as_float(lo), __uint_as_float(hi));
}

__device__ __forceinline__ float warp_sum(float v) {
    #pragma unroll
    for (int o = 16; o > 0; o >>= 1) v += __shfl_xor_sync(0xffffffffu, v, o);
    return v;
}

// -------- Threefry-2x32 (exact JAX cipher) --------
#define TF_ROUND(x0, x1, r) { x0 += x1; x1 = ((x1) << (r)) | ((x1) >> (32 - (r))); x1 ^= x0; }

__device__ __forceinline__ uint2 threefry2x32(unsigned int k0, unsigned int k1,
                                              unsigned int x0, unsigned int x1) {
    unsigned int k2 = k0 ^ k1 ^ 0x1BD11BDAu;
    x0 += k0; x1 += k1;
    TF_ROUND(x0, x1, 13) TF_ROUND(x0, x1, 15) TF_ROUND(x0, x1, 26) TF_ROUND(x0, x1, 6)
    x0 += k1; x1 += k2 + 1u;
    TF_ROUND(x0, x1, 17) TF_ROUND(x0, x1, 29) TF_ROUND(x0, x1, 16) TF_ROUND(x0, x1, 24)
    x0 += k2; x1 += k0 + 2u;
    TF_ROUND(x0, x1, 13) TF_ROUND(x0, x1, 15) TF_ROUND(x0, x1, 26) TF_ROUND(x0, x1, 6)
    x0 += k0; x1 += k1 + 3u;
    TF_ROUND(x0, x1, 17) TF_ROUND(x0, x1, 29) TF_ROUND(x0, x1, 16) TF_ROUND(x0, x1, 24)
    x0 += k1; x1 += k2 + 4u;
    TF_ROUND(x0, x1, 13) TF_ROUND(x0, x1, 15) TF_ROUND(x0, x1, 26) TF_ROUND(x0, x1, 6)
    x0 += k2; x1 += k0 + 5u;
    return make_uint2(x0, x1);
}

// ================= kernel 0: zero scratch =================
__global__ void vq_zero_kernel() {
    int i = blockIdx.x * blockDim.x + threadIdx.x;
    int stride = gridDim.x * blockDim.x;
    for (int idx = i; idx < KC * WDIM; idx += stride) g_ksum_acc[idx] = 0.0f;
    for (int idx = i; idx < KC;        idx += stride) g_kelem_acc[idx] = 0.0f;
    for (int idx = i; idx < NT;        idx += stride) g_rownorm[idx] = 0.0f;
    if (i < 8) g_red[i] = 0.0;
}

// ================= kernel R0: sort keys, threefry_partitionable semantics ======
// Modern JAX default (jax_threefry_partitionable=True):
//   split(key)[j]        = threefry(key, hi=0, lo=j)     (both output words)
//   random_bits(k,32,(n,))[i] = let c = threefry(k, 0, i) in c.x ^ c.y
// _shuffle(key(42), arange(16384)) does 2 rounds of
//   key, subkey = split(key); sort_keys = random_bits(subkey); stable sort.
__global__ void vq_rng_kernel() {
    const int i = blockIdx.x * blockDim.x + threadIdx.x;   // 0..16383
    if (i >= NT) return;
    // key chain (few hundred int ops per thread, negligible)
    uint2 k1 = threefry2x32(0u, 42u, 0u, 0u);   // round-1 carried key
    uint2 s1 = threefry2x32(0u, 42u, 0u, 1u);   // round-1 subkey
    uint2 s2 = threefry2x32(k1.x, k1.y, 0u, 1u); // round-2 subkey

    uint2 r1 = threefry2x32(s1.x, s1.y, 0u, (unsigned)i);
    g_sk1[i] = r1.x ^ r1.y;
    uint2 r2 = threefry2x32(s2.x, s2.y, 0u, (unsigned)i);
    g_sk2[i] = r2.x ^ r2.y;
}

// ================= kernels R1/R2: stable-sort via exact O(n^2) ranking ======
// lax.sort_key_val ascending + stable == rank by unique composite (key<<32 | pos).
__global__ void vq_rank1_kernel() {
    __shared__ unsigned long long s[256];
    const int i = blockIdx.x * 256 + threadIdx.x;
    const unsigned long long ci = ((unsigned long long)g_sk1[i] << 32) | (unsigned)i;
    int rank = 0;
    for (int tile = 0; tile < NT; tile += 256) {
        s[threadIdx.x] =
            ((unsigned long long)g_sk1[tile + threadIdx.x] << 32) | (unsigned)(tile + threadIdx.x);
        __syncthreads();
        #pragma unroll 16
        for (int j = 0; j < 256; j++) rank += (s[j] < ci) ? 1 : 0;
        __syncthreads();
    }
    g_v1[rank] = i;          // sorted_val[rank(i)] = val[i], val[i] = i
}
__global__ void vq_rank2_kernel() {
    __shared__ unsigned long long s[256];
    const int i = blockIdx.x * 256 + threadIdx.x;
    const unsigned long long ci = ((unsigned long long)g_sk2[i] << 32) | (unsigned)i;
    int rank = 0;
    for (int tile = 0; tile < NT; tile += 256) {
        s[threadIdx.x] =
            ((unsigned long long)g_sk2[tile + threadIdx.x] << 32) | (unsigned)(tile + threadIdx.x);
        __syncthreads();
        #pragma unroll 16
        for (int j = 0; j < 256; j++) rank += (s[j] < ci) ? 1 : 0;
        __syncthreads();
    }
    g_ind[rank] = g_v1[i];   // permuted indices; k_rand[j] = xf[g_ind[j]]
}

// ================= kernel 1: transpose x[N,W,T] -> xf[NT,W], prenorm stats, row norms ===
__global__ void vq_transpose_kernel(const float* __restrict__ x) {
    __shared__ float tile[32][33];
    __shared__ float sWs[8], sWq[8];
    const int n  = blockIdx.z;
    const int w0 = blockIdx.y * 32;
    const int t0 = blockIdx.x * 32;
    const int tx = threadIdx.x;   // 32
    const int ty = threadIdx.y;   // 8

    float ls = 0.0f, lq = 0.0f;
    #pragma unroll
    for (int i = 0; i < 4; i++) {
        int wl = ty + i * 8;
        float v = x[((size_t)n * WDIM + (w0 + wl)) * TB + t0 + tx];
        tile[wl][tx] = v;
        ls += v;
        lq += v * v;
    }
    __syncthreads();
    #pragma unroll
    for (int i = 0; i < 4; i++) {
        int tl = ty + i * 8;
        float v = tile[tx][tl];                      // w = w0+tx, t = t0+tl
        g_xf[((size_t)(n * TB + t0 + tl)) * WDIM + w0 + tx] = v;
        float s = warp_sum(v * v);                   // warp covers 32 w's of one row
        if (tx == 0) atomicAdd(&g_rownorm[n * TB + t0 + tl], s);
    }
    // block sum/sumsq -> double atomics
    ls = warp_sum(ls);
    lq = warp_sum(lq);
    if (tx == 0) { sWs[ty] = ls; sWq[ty] = lq; }
    __syncthreads();
    if (tx == 0 && ty == 0) {
        float a = 0.0f, b = 0.0f;
        #pragma unroll
        for (int j = 0; j < 8; j++) { a += sWs[j]; b += sWq[j]; }
        atomicAdd(&g_red[0], (double)a);
        atomicAdd(&g_red[1], (double)b);
    }
}

// ================= kernel 2: codebook row norms =================
__global__ void vq_knorm_kernel(const float* __restrict__ kmat) {
    const int lane = threadIdx.x & 31;
    const int warp = threadIdx.x >> 5;             // 4 warps / block
    const int c = blockIdx.x * 4 + warp;
    if (c >= KC) return;
    float s = 0.0f;
    for (int w = lane; w < WDIM; w += 32) {
        float v = kmat[(size_t)c * WDIM + w];
        s += v * v;
    }
    s = warp_sum(s);
    if (lane == 0) g_knorm[c] = s;
}

// ================= kernel 3: fused distance GEMM + argmin (f32x2) =================
// BM=64 rows/block, BN=128 codes/tile, BK=16. 256 threads, 4x8 micro-tile per thread.
__global__ void __launch_bounds__(256) vq_argmin_kernel(const float* __restrict__ kmat,
                                                        float* __restrict__ out_xl) {
    __shared__ float As[16][64];
    __shared__ float Bs[16][128];
    __shared__ float sD[64][17];
    __shared__ int   sI[64][17];

    const int tid = threadIdx.x;
    const int tx  = tid & 15;
    const int ty  = tid >> 4;
    const int rBase = blockIdx.x * 64;

    float rn[4];
    #pragma unroll
    for (int r = 0; r < 4; r++) rn[r] = g_rownorm[rBase + ty * 4 + r];

    float best[4];
    int   bidx[4];
    #pragma unroll
    for (int r = 0; r < 4; r++) { best[r] = __int_as_float(0x7f800000); bidx[r] = 0; }

    const int lrow = tid >> 2;           // 0..63
    const int lwq  = (tid & 3) * 4;      // 0,4,8,12
    const float* xfp = g_xf + (size_t)(rBase + lrow) * WDIM + lwq;
    const int bc  = tid >> 1;            // 0..127
    const int bwq = (tid & 1) * 8;       // 0 or 8

    for (int cBase = 0; cBase < KC; cBase += 128) {
        unsigned long long acc[4][4];
        #pragma unroll
        for (int r = 0; r < 4; r++)
            #pragma unroll
            for (int cc = 0; cc < 4; cc++) acc[r][cc] = 0ull;

        const float* kp = kmat + (size_t)(cBase + bc) * WDIM + bwq;

        for (int wb = 0; wb < WDIM; wb += 16) {
            float4 av = *(const float4*)(xfp + wb);
            As[lwq + 0][lrow] = av.x;
            As[lwq + 1][lrow] = av.y;
            As[lwq + 2][lrow] = av.z;
            As[lwq + 3][lrow] = av.w;
            float4 bv0 = *(const float4*)(kp + wb);
            float4 bv1 = *(const float4*)(kp + wb + 4);
            Bs[bwq + 0][bc] = bv0.x; Bs[bwq + 1][bc] = bv0.y;
            Bs[bwq + 2][bc] = bv0.z; Bs[bwq + 3][bc] = bv0.w;
            Bs[bwq + 4][bc] = bv1.x; Bs[bwq + 5][bc] = bv1.y;
            Bs[bwq + 6][bc] = bv1.z; Bs[bwq + 7][bc] = bv1.w;
            __syncthreads();

            #pragma unroll
            for (int w = 0; w < 16; w++) {
                float4 a4 = *(const float4*)&As[w][ty * 4];
                float4 b0 = *(const float4*)&Bs[w][tx * 8];
                float4 b1 = *(const float4*)&Bs[w][tx * 8 + 4];
                unsigned long long ap[4], bp[4];
                ap[0] = pack2(a4.x, a4.x); ap[1] = pack2(a4.y, a4.y);
                ap[2] = pack2(a4.z, a4.z); ap[3] = pack2(a4.w, a4.w);
                bp[0] = pack2(b0.x, b0.y); bp[1] = pack2(b0.z, b0.w);
                bp[2] = pack2(b1.x, b1.y); bp[3] = pack2(b1.z, b1.w);
                #pragma unroll
                for (int r = 0; r < 4; r++)
                    #pragma unroll
                    for (int cc = 0; cc < 4; cc++)
                        acc[r][cc] = ffma2(ap[r], bp[cc], acc[r][cc]);
            }
            __syncthreads();
        }

        // epilogue: dist = (rownorm - 2*dot) + knorm, running argmin (first-index ties)
        #pragma unroll
        for (int cc = 0; cc < 4; cc++) {
            int c0 = cBase + tx * 8 + cc * 2;
            float kn0 = g_knorm[c0];
            float kn1 = g_knorm[c0 + 1];
            #pragma unroll
            for (int r = 0; r < 4; r++) {
                float2 d = unpack2(acc[r][cc]);
                float d0 = __fadd_rn(__fadd_rn(rn[r], -__fmul_rn(2.0f, d.x)), kn0);
                float d1 = __fadd_rn(__fadd_rn(rn[r], -__fmul_rn(2.0f, d.y)), kn1);
                if (d0 < best[r]) { best[r] = d0; bidx[r] = c0; }
                if (d1 < best[r]) { best[r] = d1; bidx[r] = c0 + 1; }
            }
        }
    }

    #pragma unroll
    for (int r = 0; r < 4; r++) { sD[ty * 4 + r][tx] = best[r]; sI[ty * 4 + r][tx] = bidx[r]; }
    __syncthreads();
    if (tid < 64) {
        float bv = sD[tid][0];
        int   bi = sI[tid][0];
        #pragma unroll
        for (int j = 1; j < 16; j++) {
            float v = sD[tid][j];
            int   ii = sI[tid][j];
            if (v < bv || (v == bv && ii < bi)) { bv = v; bi = ii; }
        }
        int row = rBase + tid;
        g_xl[row] = bi;
        out_xl[row] = (float)bi;
        atomicAdd(&g_red[2], (double)bv);   // fit = mean(min_dist)
    }
}

// ================= kernel 4: x_d[n,w,t] = k[x_l[n*T+t], w] =================
__global__ void vq_xd_kernel(const float* __restrict__ kmat, float* __restrict__ out_xd) {
    __shared__ int   sj[32];
    __shared__ float kk[32][33];
    const int n  = blockIdx.z;
    const int w0 = blockIdx.y * 32;
    const int t0 = blockIdx.x * 32;
    const int tx = threadIdx.x;   // 32
    const int ty = threadIdx.y;   // 32
    if (ty == 0) sj[tx] = g_xl[n * TB + t0 + tx];
    __syncthreads();
    kk[ty][tx] = kmat[(size_t)sj[ty] * WDIM + w0 + tx];   // coalesced over w
    __syncthreads();
    out_xd[((size_t)n * WDIM + w0 + ty) * TB + t0 + tx] = kk[tx][ty];
}

// ================= kernel 5: scatter cluster stats + commit loss =================
__global__ void vq_scatter_kernel(const float* __restrict__ kmat) {
    const int lane = threadIdx.x & 31;
    const int warp = threadIdx.x >> 5;       // 8 warps / block
    const int row  = blockIdx.x * 8 + warp;
    if (row >= NT) return;
    const int j = g_xl[row];
    const float* xr = g_xf + (size_t)row * WDIM;
    const float* kr = kmat + (size_t)j * WDIM;
    float c = 0.0f;
    for (int w = lane; w < WDIM; w += 32) {
        float xv = xr[w];
        atomicAdd(&g_ksum_acc[(size_t)j * WDIM + w], xv);
        float d = xv - kr[w];
        c += d * d;
    }
    c = warp_sum(c);
    if (lane == 0) {
        atomicAdd(&g_red[3], (double)c);
        atomicAdd(&g_kelem_acc[j], 1.0f);
    }
}

// ================= kernel 6: EMA update, k_new, dk =================
__global__ void vq_knew_kernel(const float* __restrict__ kmat,
                               const float* __restrict__ ksum_in,
                               const float* __restrict__ kelem_in,
                               float* __restrict__ out_knew,
                               float* __restrict__ out_ksumnew,
                               float* __restrict__ out_kelemnew) {
    __shared__ float s_en;
    __shared__ float sred[4];
    const int j = blockIdx.x;
    const int tid = threadIdx.x;  // 128
    if (tid == 0) {
        float en = __fadd_rn(__fmul_rn(MU_F, kelem_in[j]), __fmul_rn(OMM_F, g_kelem_acc[j]));
        s_en = en;
        out_kelemnew[j] = en;
    }
    __syncthreads();
    const float en = s_en;
    const bool usage = (en >= 1.0f);   // THRESHOLD=1.0
    // empty cluster -> reference picks k_rand[j] = xf[ind[j]] from the
    // reproduced jax permutation (key 42)
    const float* krand_row = g_xf + (size_t)g_ind[j] * WDIM;
    float dks = 0.0f;
    for (int w = tid; w < WDIM; w += 128) {
        size_t idx = (size_t)j * WDIM + w;
        float ksn = __fadd_rn(__fmul_rn(MU_F, ksum_in[idx]), __fmul_rn(OMM_F, g_ksum_acc[idx]));
        out_ksumnew[idx] = ksn;
        float kn = usage ? __fdiv_rn(ksn, en) : krand_row[w];
        out_knew[idx] = kn;
        float d = kn - kmat[idx];
        dks += d * d;
    }
    dks = warp_sum(dks);
    if ((tid & 31) == 0) sred[tid >> 5] = dks;
    __syncthreads();
    if (tid == 0) {
        float t = sred[0] + sred[1] + sred[2] + sred[3];
        atomicAdd(&g_red[4], (double)t);
    }
}

// ================= kernel 7: scalars (commit, fit, prenorm, entropy, dk) ===========
__global__ void vq_final_kernel(float* __restrict__ o_scal) {
    __shared__ double sE[8];
    const int tid = threadIdx.x;   // 256
    double le = 0.0;
    for (int j = tid; j < KC; j += 256) {
        float cnt = g_kelem_acc[j];
        float p = __fdiv_rn(cnt, 16384.0f);       // sum(_k_elem) == 16384 exactly
        le += (double)(p * logf(__fadd_rn(p, 1e-8f)));
    }
    #pragma unroll
    for (int o = 16; o > 0; o >>= 1) le += __shfl_xor_sync(0xffffffffu, le, o);
    if ((tid & 31) == 0) sE[tid >> 5] = le;
    __syncthreads();
    if (tid == 0) {
        double ent = 0.0;
        #pragma unroll
        for (int j = 0; j < 8; j++) ent += sE[j];
        const double SZ = (double)NT * (double)WDIM;   // 8388608
        double mean = g_red[0] / SZ;
        o_scal[0] = (float)(g_red[3] / SZ);                        // commit_loss
        o_scal[1] = (float)(g_red[2] / (double)NT);                // fit
        o_scal[2] = (float)sqrt(g_red[1] / SZ - mean * mean);      // prenorm
        o_scal[3] = (float)(-ent);                                 // entropy
        o_scal[4] = (float)(sqrt(g_red[4]) / 1024.0);              // dk (sqrt(K*W)=1024)
    }
}

// ================= launch =================
extern "C" void kernel_launch(void* const* d_in, const int* in_sizes, int n_in,
                              void* d_out, int out_size) {
    (void)in_sizes; (void)n_in; (void)out_size;
    const float* x     = (const float*)d_in[0];   // [16,512,1024]
    const float* k     = (const float*)d_in[1];   // [2048,512]
    const float* ksum  = (const float*)d_in[2];   // [2048,512]
    const float* kelem = (const float*)d_in[3];   // [2048]
    float* out = (float*)d_out;

    vq_zero_kernel<<<1024, 256>>>();
    vq_rng_kernel<<<NT / 256, 256>>>();
    vq_rank1_kernel<<<NT / 256, 256>>>();
    vq_rank2_kernel<<<NT / 256, 256>>>();
    vq_transpose_kernel<<<dim3(TB / 32, WDIM / 32, NB), dim3(32, 8)>>>(x);
    vq_knorm_kernel<<<KC / 4, 128>>>(k);
    vq_argmin_kernel<<<NT / 64, 256>>>(k, out + O_XL);
    vq_xd_kernel<<<dim3(TB / 32, WDIM / 32, NB), dim3(32, 32)>>>(k, out + O_XD);
    vq_scatter_kernel<<<NT / 8, 256>>>(k);
    vq_knew_kernel<<<KC, 128>>>(k, ksum, kelem,
                                out + O_KNEW, out + O_KSUM, out + O_KELEM);
    vq_final_kernel<<<1, 256>>>(out + O_SCAL);
}

// round 6
// speedup vs baseline: 1.2143x; 1.2143x over previous
#include <cuda_runtime.h>
#include <math.h>

// Problem dims (fixed by the reference)
#define NT    16384          // N*T rows
#define WDIM  512            // feature dim
#define KC    2048           // codebook size
#define NB    16             // N
#define TB    1024           // T

#define MU_F   0.99f
#define OMM_F  ((float)(1.0 - 0.99))   // exact JAX constant

// Output layout (tuple flattened, float32)
#define O_XL     0
#define O_XD     16384
#define O_SCAL   8404992
#define O_KNEW   8404997
#define O_KSUM   9453573
#define O_KELEM  10502149

// -------- scratch (static device globals) --------
__device__ float  g_xf[(size_t)NT * WDIM];
__device__ float  g_rownorm[NT];
__device__ float  g_knorm[KC];
__device__ int    g_xl[NT];
__device__ float  g_ksum_acc[(size_t)KC * WDIM];
__device__ float  g_kelem_acc[KC];
__device__ double g_red[8];                      // 0 sum, 1 sumsq, 2 fit, 3 commit, 4 dk
// permutation machinery (jax.random.permutation(key(42), xf) reproduction)
__device__ unsigned int g_sk1[NT];
__device__ unsigned int g_sk2[NT];
__device__ int    g_rank1[NT];
__device__ int    g_rank2[NT];
__device__ int    g_v1[NT];
__device__ int    g_ind[NT];

// -------- f32x2 packed-FMA helpers (Blackwell dual fp32) --------
__device__ __forceinline__ unsigned long long ffma2(unsigned long long a,
                                                    unsigned long long b,
                                                    unsigned long long c) {
    unsigned long long d;
    asm("fma.rn.f32x2 %0, %1, %2, %3;" : "=l"(d) : "l"(a), "l"(b), "l"(c));
    return d;
}
__device__ __forceinline__ unsigned long long pack2(float lo, float hi) {
    unsigned long long d;
    asm("mov.b64 %0, {%1, %2};" : "=l"(d)
        : "r"(__float_as_uint(lo)), "r"(__float_as_uint(hi)));
    return d;
}
__device__ __forceinline__ float2 unpack2(unsigned long long v) {
    unsigned int lo, hi;
    asm("mov.b64 {%0, %1}, %2;" : "=r"(lo), "=r"(hi) : "l"(v));
    return make_float2(__uint_as_float(lo), __uint_as_float(hi));
}

__device__ __forceinline__ float warp_sum(float v) {
    #pragma unroll
    for (int o = 16; o > 0; o >>= 1) v += __shfl_xor_sync(0xffffffffu, v, o);
    return v;
}

// -------- Threefry-2x32 (exact JAX cipher) --------
#define TF_ROUND(x0, x1, r) { x0 += x1; x1 = ((x1) << (r)) | ((x1) >> (32 - (r))); x1 ^= x0; }

__device__ __forceinline__ uint2 threefry2x32(unsigned int k0, unsigned int k1,
                                              unsigned int x0, unsigned int x1) {
    unsigned int k2 = k0 ^ k1 ^ 0x1BD11BDAu;
    x0 += k0; x1 += k1;
    TF_ROUND(x0, x1, 13) TF_ROUND(x0, x1, 15) TF_ROUND(x0, x1, 26) TF_ROUND(x0, x1, 6)
    x0 += k1; x1 += k2 + 1u;
    TF_ROUND(x0, x1, 17) TF_ROUND(x0, x1, 29) TF_ROUND(x0, x1, 16) TF_ROUND(x0, x1, 24)
    x0 += k2; x1 += k0 + 2u;
    TF_ROUND(x0, x1, 13) TF_ROUND(x0, x1, 15) TF_ROUND(x0, x1, 26) TF_ROUND(x0, x1, 6)
    x0 += k0; x1 += k1 + 3u;
    TF_ROUND(x0, x1, 17) TF_ROUND(x0, x1, 29) TF_ROUND(x0, x1, 16) TF_ROUND(x0, x1, 24)
    x0 += k1; x1 += k2 + 4u;
    TF_ROUND(x0, x1, 13) TF_ROUND(x0, x1, 15) TF_ROUND(x0, x1, 26) TF_ROUND(x0, x1, 6)
    x0 += k2; x1 += k0 + 5u;
    return make_uint2(x0, x1);
}

// ================= kernel 0: zero scratch =================
__global__ void vq_zero_kernel() {
    int i = blockIdx.x * blockDim.x + threadIdx.x;
    int stride = gridDim.x * blockDim.x;
    for (int idx = i; idx < KC * WDIM; idx += stride) g_ksum_acc[idx] = 0.0f;
    for (int idx = i; idx < KC;        idx += stride) g_kelem_acc[idx] = 0.0f;
    for (int idx = i; idx < NT;        idx += stride) {
        g_rownorm[idx] = 0.0f;
        g_rank1[idx] = 0;
        g_rank2[idx] = 0;
    }
    if (i < 8) g_red[i] = 0.0;
}

// ================= kernel R0: sort keys, threefry_partitionable semantics ======
__global__ void vq_rng_kernel() {
    const int i = blockIdx.x * blockDim.x + threadIdx.x;   // 0..16383
    if (i >= NT) return;
    uint2 k1 = threefry2x32(0u, 42u, 0u, 0u);    // round-1 carried key
    uint2 s1 = threefry2x32(0u, 42u, 0u, 1u);    // round-1 subkey
    uint2 s2 = threefry2x32(k1.x, k1.y, 0u, 1u); // round-2 subkey

    uint2 r1 = threefry2x32(s1.x, s1.y, 0u, (unsigned)i);
    g_sk1[i] = r1.x ^ r1.y;
    uint2 r2 = threefry2x32(s2.x, s2.y, 0u, (unsigned)i);
    g_sk2[i] = r2.x ^ r2.y;
}

// ================= kernel R1: partial stable-sort ranks (full-chip) =========
// grid (64, 8, 2): x = element group, y = column slice, z = round.
// rank by unique composite (key<<32 | pos) == stable ascending sort.
__global__ void vq_rank_partial_kernel() {
    __shared__ unsigned long long s[2048];
    const unsigned int* sk = (blockIdx.z == 0) ? g_sk1 : g_sk2;
    int* grank             = (blockIdx.z == 0) ? g_rank1 : g_rank2;
    const int i  = blockIdx.x * 256 + threadIdx.x;
    const int c0 = blockIdx.y * 2048;
    for (int j = threadIdx.x; j < 2048; j += 256)
        s[j] = ((unsigned long long)sk[c0 + j] << 32) | (unsigned)(c0 + j);
    __syncthreads();
    const unsigned long long ci = ((unsigned long long)sk[i] << 32) | (unsigned)i;
    int cnt = 0;
    #pragma unroll 16
    for (int j = 0; j < 2048; j++) cnt += (s[j] < ci) ? 1 : 0;
    atomicAdd(&grank[i], cnt);
}

__global__ void vq_perm_scatter1_kernel() {
    const int i = blockIdx.x * 256 + threadIdx.x;
    g_v1[g_rank1[i]] = i;              // round-1: sorted_val[rank] = i
}
__global__ void vq_perm_scatter2_kernel() {
    const int i = blockIdx.x * 256 + threadIdx.x;
    g_ind[g_rank2[i]] = g_v1[i];       // round-2: k_rand[j] = xf[g_ind[j]]
}

// ================= kernel 1: transpose x[N,W,T] -> xf[NT,W] + stats =========
__global__ void vq_transpose_kernel(const float* __restrict__ x) {
    __shared__ float tile[32][33];
    __shared__ float sWs[8], sWq[8];
    const int n  = blockIdx.z;
    const int w0 = blockIdx.y * 32;
    const int t0 = blockIdx.x * 32;
    const int tx = threadIdx.x;   // 32
    const int ty = threadIdx.y;   // 8

    float ls = 0.0f, lq = 0.0f;
    #pragma unroll
    for (int i = 0; i < 4; i++) {
        int wl = ty + i * 8;
        float v = x[((size_t)n * WDIM + (w0 + wl)) * TB + t0 + tx];
        tile[wl][tx] = v;
        ls += v;
        lq += v * v;
    }
    __syncthreads();
    #pragma unroll
    for (int i = 0; i < 4; i++) {
        int tl = ty + i * 8;
        float v = tile[tx][tl];                      // w = w0+tx, t = t0+tl
        g_xf[((size_t)(n * TB + t0 + tl)) * WDIM + w0 + tx] = v;
        float s = warp_sum(v * v);
        if (tx == 0) atomicAdd(&g_rownorm[n * TB + t0 + tl], s);
    }
    ls = warp_sum(ls);
    lq = warp_sum(lq);
    if (tx == 0) { sWs[ty] = ls; sWq[ty] = lq; }
    __syncthreads();
    if (tx == 0 && ty == 0) {
        float a = 0.0f, b = 0.0f;
        #pragma unroll
        for (int j = 0; j < 8; j++) { a += sWs[j]; b += sWq[j]; }
        atomicAdd(&g_red[0], (double)a);
        atomicAdd(&g_red[1], (double)b);
    }
}

// ================= kernel 2: codebook row norms =================
__global__ void vq_knorm_kernel(const float* __restrict__ kmat) {
    const int lane = threadIdx.x & 31;
    const int warp = threadIdx.x >> 5;
    const int c = blockIdx.x * 4 + warp;
    if (c >= KC) return;
    float s = 0.0f;
    for (int w = lane; w < WDIM; w += 32) {
        float v = kmat[(size_t)c * WDIM + w];
        s += v * v;
    }
    s = warp_sum(s);
    if (lane == 0) g_knorm[c] = s;
}

// ================= kernel 3: fused distance GEMM + argmin (f32x2) ==========
// BM=128 rows/block, BN=128 codes/tile, BK=16, 256 threads, 8x8 micro-tile.
// Row-paired f32x2 lanes: a-pairs come free from LDS.128 (register pairs),
// b loaded as 8 conflict-free scalar LDS (strided cols) and splatted.
// Double-buffered smem, one __syncthreads per K-step.
#define AS_STRIDE 132   // padded: 16B-aligned rows, reduced STS conflicts

__global__ void __launch_bounds__(256) vq_argmin_kernel(const float* __restrict__ kmat,
                                                        float* __restrict__ out_xl) {
    __shared__ union SmU {
        struct { float As[2][16][AS_STRIDE]; float Bs[2][16][AS_STRIDE]; } m;
        struct { float sD[128][17]; int sI[128][17]; } r;
    } sm;

    const int tid = threadIdx.x;
    const int tx  = tid & 15;            // col group (strided cols tx + 16m)
    const int ty  = tid >> 4;            // row group (rows ty*8 .. ty*8+7)
    const int rBase = blockIdx.x * 128;

    // staging: 512 float4 per operand tile, 2 per thread
    const int row0 = tid >> 1;                  // 0..127
    const int wq0  = (tid & 1) * 4;             // 0 or 4
    const int wq1  = wq0 + 8;                   // 8 or 12

    float rn[8];
    #pragma unroll
    for (int r = 0; r < 8; r++) rn[r] = g_rownorm[rBase + ty * 8 + r];

    float best[8];
    int   bidx[8];
    #pragma unroll
    for (int r = 0; r < 8; r++) { best[r] = __int_as_float(0x7f800000); bidx[r] = 0; }

    const float* Abase = g_xf + (size_t)rBase * WDIM;

    for (int ct = 0; ct < 16; ct++) {
        const int cBase = ct * 128;
        const float* Bbase = kmat + (size_t)cBase * WDIM;

        unsigned long long acc[4][8];
        #pragma unroll
        for (int r = 0; r < 4; r++)
            #pragma unroll
            for (int m = 0; m < 8; m++) acc[r][m] = 0ull;

        float4 pa0, pa1, pb0, pb1;

        #define LDG_STAGE(wb) {                                                   \
            pa0 = *(const float4*)(Abase + (size_t)row0 * WDIM + (wb) + wq0);     \
            pa1 = *(const float4*)(Abase + (size_t)row0 * WDIM + (wb) + wq1);     \
            pb0 = *(const float4*)(Bbase + (size_t)row0 * WDIM + (wb) + wq0);     \
            pb1 = *(const float4*)(Bbase + (size_t)row0 * WDIM + (wb) + wq1);     \
        }
        #define STS_STAGE(buf) {                                                  \
            sm.m.As[buf][wq0 + 0][row0] = pa0.x; sm.m.As[buf][wq0 + 1][row0] = pa0.y; \
            sm.m.As[buf][wq0 + 2][row0] = pa0.z; sm.m.As[buf][wq0 + 3][row0] = pa0.w; \
            sm.m.As[buf][wq1 + 0][row0] = pa1.x; sm.m.As[buf][wq1 + 1][row0] = pa1.y; \
            sm.m.As[buf][wq1 + 2][row0] = pa1.z; sm.m.As[buf][wq1 + 3][row0] = pa1.w; \
            sm.m.Bs[buf][wq0 + 0][row0] = pb0.x; sm.m.Bs[buf][wq0 + 1][row0] = pb0.y; \
            sm.m.Bs[buf][wq0 + 2][row0] = pb0.z; sm.m.Bs[buf][wq0 + 3][row0] = pb0.w; \
            sm.m.Bs[buf][wq1 + 0][row0] = pb1.x; sm.m.Bs[buf][wq1 + 1][row0] = pb1.y; \
            sm.m.Bs[buf][wq1 + 2][row0] = pb1.z; sm.m.Bs[buf][wq1 + 3][row0] = pb1.w; \
        }

        LDG_STAGE(0);
        STS_STAGE(0);
        LDG_STAGE(16);
        __syncthreads();

        #pragma unroll 1
        for (int kb = 0; kb < 32; kb++) {
            const int cur = kb & 1;
            #pragma unroll
            for (int w = 0; w < 16; w++) {
                ulonglong2 a01 = *(const ulonglong2*)&sm.m.As[cur][w][ty * 8];
                ulonglong2 a23 = *(const ulonglong2*)&sm.m.As[cur][w][ty * 8 + 4];
                #pragma unroll
                for (int m = 0; m < 8; m++) {
                    float bsc = sm.m.Bs[cur][w][tx + 16 * m];
                    unsigned long long bs = pack2(bsc, bsc);
                    acc[0][m] = ffma2(a01.x, bs, acc[0][m]);
                    acc[1][m] = ffma2(a01.y, bs, acc[1][m]);
                    acc[2][m] = ffma2(a23.x, bs, acc[2][m]);
                    acc[3][m] = ffma2(a23.y, bs, acc[3][m]);
                }
            }
            if (kb < 31) {
                STS_STAGE(cur ^ 1);
                if (kb < 30) LDG_STAGE((kb + 2) * 16);
                __syncthreads();
            }
        }

        // epilogue: dist = (rownorm - 2*dot) + knorm, running argmin
        // within-thread col order ascending (ct asc, m asc) -> strict < keeps first
        #pragma unroll
        for (int m = 0; m < 8; m++) {
            const int col = cBase + tx + 16 * m;
            const float kn = g_knorm[col];
            #pragma unroll
            for (int r = 0; r < 4; r++) {
                float2 d = unpack2(acc[r][m]);
                float d0 = __fadd_rn(__fadd_rn(rn[2 * r],     -__fmul_rn(2.0f, d.x)), kn);
                float d1 = __fadd_rn(__fadd_rn(rn[2 * r + 1], -__fmul_rn(2.0f, d.y)), kn);
                if (d0 < best[2 * r])     { best[2 * r]     = d0; bidx[2 * r]     = col; }
                if (d1 < best[2 * r + 1]) { best[2 * r + 1] = d1; bidx[2 * r + 1] = col; }
            }
        }
        __syncthreads();   // protect smem buffers before next ct's prologue STS
        #undef LDG_STAGE
        #undef STS_STAGE
    }

    // cross-thread reduction over the 16 tx groups (union aliases mainloop smem)
    #pragma unroll
    for (int r = 0; r < 8; r++) {
        sm.r.sD[ty * 8 + r][tx] = best[r];
        sm.r.sI[ty * 8 + r][tx] = bidx[r];
    }
    __syncthreads();
    if (tid < 128) {
        float bv = sm.r.sD[tid][0];
        int   bi = sm.r.sI[tid][0];
        #pragma unroll
        for (int j = 1; j < 16; j++) {
            float v  = sm.r.sD[tid][j];
            int   ii = sm.r.sI[tid][j];
            if (v < bv || (v == bv && ii < bi)) { bv = v; bi = ii; }
        }
        const int row = rBase + tid;
        g_xl[row] = bi;
        out_xl[row] = (float)bi;
        atomicAdd(&g_red[2], (double)bv);   // fit = mean(min_dist)
    }
}

// ================= kernel 4: x_d[n,w,t] = k[x_l[n*T+t], w] =================
__global__ void vq_xd_kernel(const float* __restrict__ kmat, float* __restrict__ out_xd) {
    __shared__ int   sj[32];
    __shared__ float kk[32][33];
    const int n  = blockIdx.z;
    const int w0 = blockIdx.y * 32;
    const int t0 = blockIdx.x * 32;
    const int tx = threadIdx.x;
    const int ty = threadIdx.y;
    if (ty == 0) sj[tx] = g_xl[n * TB + t0 + tx];
    __syncthreads();
    kk[ty][tx] = kmat[(size_t)sj[ty] * WDIM + w0 + tx];
    __syncthreads();
    out_xd[((size_t)n * WDIM + w0 + ty) * TB + t0 + tx] = kk[tx][ty];
}

// ================= kernel 5: scatter cluster stats + commit loss ============
__global__ void vq_scatter_kernel(const float* __restrict__ kmat) {
    const int lane = threadIdx.x & 31;
    const int warp = threadIdx.x >> 5;
    const int row  = blockIdx.x * 8 + warp;
    if (row >= NT) return;
    const int j = g_xl[row];
    const float* xr = g_xf + (size_t)row * WDIM;
    const float* kr = kmat + (size_t)j * WDIM;
    float c = 0.0f;
    for (int w = lane; w < WDIM; w += 32) {
        float xv = xr[w];
        atomicAdd(&g_ksum_acc[(size_t)j * WDIM + w], xv);
        float d = xv - kr[w];
        c += d * d;
    }
    c = warp_sum(c);
    if (lane == 0) {
        atomicAdd(&g_red[3], (double)c);
        atomicAdd(&g_kelem_acc[j], 1.0f);
    }
}

// ================= kernel 6: EMA update, k_new, dk =================
__global__ void vq_knew_kernel(const float* __restrict__ kmat,
                               const float* __restrict__ ksum_in,
                               const float* __restrict__ kelem_in,
                               float* __restrict__ out_knew,
                               float* __restrict__ out_ksumnew,
                               float* __restrict__ out_kelemnew) {
    __shared__ float s_en;
    __shared__ float sred[4];
    const int j = blockIdx.x;
    const int tid = threadIdx.x;  // 128
    if (tid == 0) {
        float en = __fadd_rn(__fmul_rn(MU_F, kelem_in[j]), __fmul_rn(OMM_F, g_kelem_acc[j]));
        s_en = en;
        out_kelemnew[j] = en;
    }
    __syncthreads();
    const float en = s_en;
    const bool usage = (en >= 1.0f);   // THRESHOLD=1.0
    const float* krand_row = g_xf + (size_t)g_ind[j] * WDIM;
    float dks = 0.0f;
    for (int w = tid; w < WDIM; w += 128) {
        size_t idx = (size_t)j * WDIM + w;
        float ksn = __fadd_rn(__fmul_rn(MU_F, ksum_in[idx]), __fmul_rn(OMM_F, g_ksum_acc[idx]));
        out_ksumnew[idx] = ksn;
        float kn = usage ? __fdiv_rn(ksn, en) : krand_row[w];
        out_knew[idx] = kn;
        float d = kn - kmat[idx];
        dks += d * d;
    }
    dks = warp_sum(dks);
    if ((tid & 31) == 0) sred[tid >> 5] = dks;
    __syncthreads();
    if (tid == 0) {
        float t = sred[0] + sred[1] + sred[2] + sred[3];
        atomicAdd(&g_red[4], (double)t);
    }
}

// ================= kernel 7: scalars =================
__global__ void vq_final_kernel(float* __restrict__ o_scal) {
    __shared__ double sE[8];
    const int tid = threadIdx.x;   // 256
    double le = 0.0;
    for (int j = tid; j < KC; j += 256) {
        float cnt = g_kelem_acc[j];
        float p = __fdiv_rn(cnt, 16384.0f);
        le += (double)(p * logf(__fadd_rn(p, 1e-8f)));
    }
    #pragma unroll
    for (int o = 16; o > 0; o >>= 1) le += __shfl_xor_sync(0xffffffffu, le, o);
    if ((tid & 31) == 0) sE[tid >> 5] = le;
    __syncthreads();
    if (tid == 0) {
        double ent = 0.0;
        #pragma unroll
        for (int j = 0; j < 8; j++) ent += sE[j];
        const double SZ = (double)NT * (double)WDIM;
        double mean = g_red[0] / SZ;
        o_scal[0] = (float)(g_red[3] / SZ);                    // commit_loss
        o_scal[1] = (float)(g_red[2] / (double)NT);            // fit
        o_scal[2] = (float)sqrt(g_red[1] / SZ - mean * mean);  // prenorm
        o_scal[3] = (float)(-ent);                             // entropy
        o_scal[4] = (float)(sqrt(g_red[4]) / 1024.0);          // dk
    }
}

// ================= launch =================
extern "C" void kernel_launch(void* const* d_in, const int* in_sizes, int n_in,
                              void* d_out, int out_size) {
    (void)in_sizes; (void)n_in; (void)out_size;
    const float* x     = (const float*)d_in[0];   // [16,512,1024]
    const float* k     = (const float*)d_in[1];   // [2048,512]
    const float* ksum  = (const float*)d_in[2];   // [2048,512]
    const float* kelem = (const float*)d_in[3];   // [2048]
    float* out = (float*)d_out;

    vq_zero_kernel<<<1024, 256>>>();
    vq_rng_kernel<<<NT / 256, 256>>>();
    vq_rank_partial_kernel<<<dim3(64, 8, 2), 256>>>();
    vq_perm_scatter1_kernel<<<NT / 256, 256>>>();
    vq_perm_scatter2_kernel<<<NT / 256, 256>>>();
    vq_transpose_kernel<<<dim3(TB / 32, WDIM / 32, NB), dim3(32, 8)>>>(x);
    vq_knorm_kernel<<<KC / 4, 128>>>(k);
    vq_argmin_kernel<<<NT / 128, 256>>>(k, out + O_XL);
    vq_xd_kernel<<<dim3(TB / 32, WDIM / 32, NB), dim3(32, 32)>>>(k, out + O_XD);
    vq_scatter_kernel<<<NT / 8, 256>>>(k);
    vq_knew_kernel<<<KC, 128>>>(k, ksum, kelem,
                                out + O_KNEW, out + O_KSUM, out + O_KELEM);
    vq_final_kernel<<<1, 256>>>(out + O_SCAL);
}

// round 7
// speedup vs baseline: 1.5449x; 1.2722x over previous
#include <cuda_runtime.h>
#include <math.h>

// Problem dims (fixed by the reference)
#define NT    16384          // N*T rows
#define WDIM  512            // feature dim
#define KC    2048           // codebook size
#define NB    16             // N
#define TB    1024           // T

#define MU_F   0.99f
#define OMM_F  ((float)(1.0 - 0.99))   // exact JAX constant

// Output layout (tuple flattened, float32)
#define O_XL     0
#define O_XD     16384
#define O_SCAL   8404992
#define O_KNEW   8404997
#define O_KSUM   9453573
#define O_KELEM  10502149

// -------- scratch (static device globals) --------
__device__ float  g_xf[(size_t)NT * WDIM];
__device__ float  g_rownorm[NT];
__device__ float  g_knorm[KC];
__device__ int    g_xl[NT];
__device__ unsigned long long g_best[NT];        // (monotone distbits)<<32 | idx
__device__ float  g_ksum_acc[(size_t)KC * WDIM];
__device__ float  g_kelem_acc[KC];
__device__ double g_red[8];                      // 0 sum, 1 sumsq, 2 fit, 3 commit, 4 dk
// permutation machinery (jax.random.permutation(key(42), xf) reproduction)
__device__ unsigned int g_sk1[NT];
__device__ unsigned int g_sk2[NT];
__device__ int    g_rank1[NT];
__device__ int    g_rank2[NT];
__device__ int    g_v1[NT];
__device__ int    g_ind[NT];

// -------- f32x2 packed-FMA helpers (Blackwell dual fp32) --------
__device__ __forceinline__ unsigned long long ffma2(unsigned long long a,
                                                    unsigned long long b,
                                                    unsigned long long c) {
    unsigned long long d;
    asm("fma.rn.f32x2 %0, %1, %2, %3;" : "=l"(d) : "l"(a), "l"(b), "l"(c));
    return d;
}
__device__ __forceinline__ unsigned long long pack2(float lo, float hi) {
    unsigned long long d;
    asm("mov.b64 %0, {%1, %2};" : "=l"(d)
        : "r"(__float_as_uint(lo)), "r"(__float_as_uint(hi)));
    return d;
}
__device__ __forceinline__ float2 unpack2(unsigned long long v) {
    unsigned int lo, hi;
    asm("mov.b64 {%0, %1}, %2;" : "=r"(lo), "=r"(hi) : "l"(v));
    return make_float2(__uint_as_float(lo), __uint_as_float(hi));
}

__device__ __forceinline__ float warp_sum(float v) {
    #pragma unroll
    for (int o = 16; o > 0; o >>= 1) v += __shfl_xor_sync(0xffffffffu, v, o);
    return v;
}
__device__ __forceinline__ double warp_sum_d(double v) {
    #pragma unroll
    for (int o = 16; o > 0; o >>= 1) v += __shfl_xor_sync(0xffffffffu, v, o);
    return v;
}

// monotone float->uint map (order-preserving for all finite floats)
__device__ __forceinline__ unsigned int fmono(float f) {
    unsigned int b = __float_as_uint(f);
    return (b & 0x80000000u) ? ~b : (b | 0x80000000u);
}
__device__ __forceinline__ float fmono_inv(unsigned int u) {
    unsigned int b = (u & 0x80000000u) ? (u & 0x7FFFFFFFu) : ~u;
    return __uint_as_float(b);
}

// -------- Threefry-2x32 (exact JAX cipher) --------
#define TF_ROUND(x0, x1, r) { x0 += x1; x1 = ((x1) << (r)) | ((x1) >> (32 - (r))); x1 ^= x0; }

__device__ __forceinline__ uint2 threefry2x32(unsigned int k0, unsigned int k1,
                                              unsigned int x0, unsigned int x1) {
    unsigned int k2 = k0 ^ k1 ^ 0x1BD11BDAu;
    x0 += k0; x1 += k1;
    TF_ROUND(x0, x1, 13) TF_ROUND(x0, x1, 15) TF_ROUND(x0, x1, 26) TF_ROUND(x0, x1, 6)
    x0 += k1; x1 += k2 + 1u;
    TF_ROUND(x0, x1, 17) TF_ROUND(x0, x1, 29) TF_ROUND(x0, x1, 16) TF_ROUND(x0, x1, 24)
    x0 += k2; x1 += k0 + 2u;
    TF_ROUND(x0, x1, 13) TF_ROUND(x0, x1, 15) TF_ROUND(x0, x1, 26) TF_ROUND(x0, x1, 6)
    x0 += k0; x1 += k1 + 3u;
    TF_ROUND(x0, x1, 17) TF_ROUND(x0, x1, 29) TF_ROUND(x0, x1, 16) TF_ROUND(x0, x1, 24)
    x0 += k1; x1 += k2 + 4u;
    TF_ROUND(x0, x1, 13) TF_ROUND(x0, x1, 15) TF_ROUND(x0, x1, 26) TF_ROUND(x0, x1, 6)
    x0 += k2; x1 += k0 + 5u;
    return make_uint2(x0, x1);
}

// ================= kernel 0: zero scratch =================
__global__ void vq_zero_kernel() {
    int i = blockIdx.x * blockDim.x + threadIdx.x;
    int stride = gridDim.x * blockDim.x;
    for (int idx = i; idx < KC * WDIM; idx += stride) g_ksum_acc[idx] = 0.0f;
    for (int idx = i; idx < KC;        idx += stride) g_kelem_acc[idx] = 0.0f;
    for (int idx = i; idx < NT;        idx += stride) {
        g_rownorm[idx] = 0.0f;
        g_rank1[idx] = 0;
        g_rank2[idx] = 0;
        g_best[idx] = 0xFFFFFFFFFFFFFFFFull;
    }
    if (i < 8) g_red[i] = 0.0;
}

// ================= kernel R0: sort keys, threefry_partitionable semantics ======
__global__ void vq_rng_kernel() {
    const int i = blockIdx.x * blockDim.x + threadIdx.x;   // 0..16383
    if (i >= NT) return;
    uint2 k1 = threefry2x32(0u, 42u, 0u, 0u);    // round-1 carried key
    uint2 s1 = threefry2x32(0u, 42u, 0u, 1u);    // round-1 subkey
    uint2 s2 = threefry2x32(k1.x, k1.y, 0u, 1u); // round-2 subkey

    uint2 r1 = threefry2x32(s1.x, s1.y, 0u, (unsigned)i);
    g_sk1[i] = r1.x ^ r1.y;
    uint2 r2 = threefry2x32(s2.x, s2.y, 0u, (unsigned)i);
    g_sk2[i] = r2.x ^ r2.y;
}

// ================= kernel R1: partial stable-sort ranks (full-chip) =========
__global__ void vq_rank_partial_kernel() {
    __shared__ unsigned long long s[2048];
    const unsigned int* sk = (blockIdx.z == 0) ? g_sk1 : g_sk2;
    int* grank             = (blockIdx.z == 0) ? g_rank1 : g_rank2;
    const int i  = blockIdx.x * 256 + threadIdx.x;
    const int c0 = blockIdx.y * 2048;
    for (int j = threadIdx.x; j < 2048; j += 256)
        s[j] = ((unsigned long long)sk[c0 + j] << 32) | (unsigned)(c0 + j);
    __syncthreads();
    const unsigned long long ci = ((unsigned long long)sk[i] << 32) | (unsigned)i;
    int cnt = 0;
    #pragma unroll 16
    for (int j = 0; j < 2048; j++) cnt += (s[j] < ci) ? 1 : 0;
    atomicAdd(&grank[i], cnt);
}

__global__ void vq_perm_scatter1_kernel() {
    const int i = blockIdx.x * 256 + threadIdx.x;
    g_v1[g_rank1[i]] = i;              // round-1: sorted_val[rank] = i
}
__global__ void vq_perm_scatter2_kernel() {
    const int i = blockIdx.x * 256 + threadIdx.x;
    g_ind[g_rank2[i]] = g_v1[i];       // round-2: k_rand[j] = xf[g_ind[j]]
}

// ================= kernel 1: transpose x[N,W,T] -> xf[NT,W] + stats =========
__global__ void vq_transpose_kernel(const float* __restrict__ x) {
    __shared__ float tile[32][33];
    __shared__ float sWs[8], sWq[8];
    const int n  = blockIdx.z;
    const int w0 = blockIdx.y * 32;
    const int t0 = blockIdx.x * 32;
    const int tx = threadIdx.x;   // 32
    const int ty = threadIdx.y;   // 8

    float ls = 0.0f, lq = 0.0f;
    #pragma unroll
    for (int i = 0; i < 4; i++) {
        int wl = ty + i * 8;
        float v = x[((size_t)n * WDIM + (w0 + wl)) * TB + t0 + tx];
        tile[wl][tx] = v;
        ls += v;
        lq += v * v;
    }
    __syncthreads();
    #pragma unroll
    for (int i = 0; i < 4; i++) {
        int tl = ty + i * 8;
        float v = tile[tx][tl];                      // w = w0+tx, t = t0+tl
        g_xf[((size_t)(n * TB + t0 + tl)) * WDIM + w0 + tx] = v;
        float s = warp_sum(v * v);
        if (tx == 0) atomicAdd(&g_rownorm[n * TB + t0 + tl], s);
    }
    ls = warp_sum(ls);
    lq = warp_sum(lq);
    if (tx == 0) { sWs[ty] = ls; sWq[ty] = lq; }
    __syncthreads();
    if (tx == 0 && ty == 0) {
        float a = 0.0f, b = 0.0f;
        #pragma unroll
        for (int j = 0; j < 8; j++) { a += sWs[j]; b += sWq[j]; }
        atomicAdd(&g_red[0], (double)a);
        atomicAdd(&g_red[1], (double)b);
    }
}

// ================= kernel 2: codebook row norms =================
__global__ void vq_knorm_kernel(const float* __restrict__ kmat) {
    const int lane = threadIdx.x & 31;
    const int warp = threadIdx.x >> 5;
    const int c = blockIdx.x * 4 + warp;
    if (c >= KC) return;
    float s = 0.0f;
    for (int w = lane; w < WDIM; w += 32) {
        float v = kmat[(size_t)c * WDIM + w];
        s += v * v;
    }
    s = warp_sum(s);
    if (lane == 0) g_knorm[c] = s;
}

// ================= kernel 3: fused distance GEMM + argmin (f32x2) ==========
// grid (NT/128, 2): x = 128-row block, y = 1024-code half (for 2 blocks/SM).
// BM=128, BN=128/tile, BK=16, 256 threads, 8 rows x 8 cols per thread.
// B stored DUPLICATED in smem so the splat is a single LDS.64 into a register
// pair (zero pack-MOVs in the inner loop). A pairs come free via LDS.128.
// Cross-block argmin combine via packed u64 atomicMin (min-idx tie-break ==
// reference's first-index rule; dist bits identical: same sequential-w order).
__global__ void __launch_bounds__(256, 2) vq_argmin_kernel(const float* __restrict__ kmat) {
    __shared__ union SmU {
        struct { float As[2][16][128]; float Bs[2][16][256]; } m;   // 49152 B
        struct { float sD[128][17]; int sI[128][17]; } r;
    } sm;

    const int tid = threadIdx.x;
    const int tx  = tid & 15;            // col group (cols tx + 16m)
    const int ty  = tid >> 4;            // row group (rows ty*8 .. ty*8+7)
    const int rBase = blockIdx.x * 128;
    const int cBase0 = blockIdx.y * 1024;

    const int row0 = tid >> 1;                  // 0..127 (staging row)
    const int wq0  = (tid & 1) * 4;             // 0 or 4
    const int wq1  = wq0 + 8;                   // 8 or 12

    float rn[8];
    #pragma unroll
    for (int r = 0; r < 8; r++) rn[r] = g_rownorm[rBase + ty * 8 + r];

    float best[8];
    int   bidx[8];
    #pragma unroll
    for (int r = 0; r < 8; r++) { best[r] = __int_as_float(0x7f800000); bidx[r] = 0; }

    const float* Abase = g_xf + (size_t)rBase * WDIM;

    for (int ct = 0; ct < 8; ct++) {
        const int cBase = cBase0 + ct * 128;
        const float* Bbase = kmat + (size_t)cBase * WDIM;

        unsigned long long acc[4][8];
        #pragma unroll
        for (int r = 0; r < 4; r++)
            #pragma unroll
            for (int m = 0; m < 8; m++) acc[r][m] = 0ull;

        float4 pa0, pa1, pb0, pb1;

        #define LDG_STAGE(wb) {                                                   \
            pa0 = *(const float4*)(Abase + (size_t)row0 * WDIM + (wb) + wq0);     \
            pa1 = *(const float4*)(Abase + (size_t)row0 * WDIM + (wb) + wq1);     \
            pb0 = *(const float4*)(Bbase + (size_t)row0 * WDIM + (wb) + wq0);     \
            pb1 = *(const float4*)(Bbase + (size_t)row0 * WDIM + (wb) + wq1);     \
        }
        #define STS_STAGE(buf) {                                                  \
            sm.m.As[buf][wq0 + 0][row0] = pa0.x; sm.m.As[buf][wq0 + 1][row0] = pa0.y; \
            sm.m.As[buf][wq0 + 2][row0] = pa0.z; sm.m.As[buf][wq0 + 3][row0] = pa0.w; \
            sm.m.As[buf][wq1 + 0][row0] = pa1.x; sm.m.As[buf][wq1 + 1][row0] = pa1.y; \
            sm.m.As[buf][wq1 + 2][row0] = pa1.z; sm.m.As[buf][wq1 + 3][row0] = pa1.w; \
            *(unsigned long long*)&sm.m.Bs[buf][wq0 + 0][2 * row0] = pack2(pb0.x, pb0.x); \
            *(unsigned long long*)&sm.m.Bs[buf][wq0 + 1][2 * row0] = pack2(pb0.y, pb0.y); \
            *(unsigned long long*)&sm.m.Bs[buf][wq0 + 2][2 * row0] = pack2(pb0.z, pb0.z); \
            *(unsigned long long*)&sm.m.Bs[buf][wq0 + 3][2 * row0] = pack2(pb0.w, pb0.w); \
            *(unsigned long long*)&sm.m.Bs[buf][wq1 + 0][2 * row0] = pack2(pb1.x, pb1.x); \
            *(unsigned long long*)&sm.m.Bs[buf][wq1 + 1][2 * row0] = pack2(pb1.y, pb1.y); \
            *(unsigned long long*)&sm.m.Bs[buf][wq1 + 2][2 * row0] = pack2(pb1.z, pb1.z); \
            *(unsigned long long*)&sm.m.Bs[buf][wq1 + 3][2 * row0] = pack2(pb1.w, pb1.w); \
        }

        LDG_STAGE(0);
        STS_STAGE(0);
        LDG_STAGE(16);
        __syncthreads();

        #pragma unroll 1
        for (int kb = 0; kb < 32; kb++) {
            const int cur = kb & 1;
            #pragma unroll
            for (int w = 0; w < 16; w++) {
                ulonglong2 a01 = *(const ulonglong2*)&sm.m.As[cur][w][ty * 8];
                ulonglong2 a23 = *(const ulonglong2*)&sm.m.As[cur][w][ty * 8 + 4];
                #pragma unroll
                for (int m = 0; m < 8; m++) {
                    unsigned long long bs =
                        *(const unsigned long long*)&sm.m.Bs[cur][w][2 * (tx + 16 * m)];
                    acc[0][m] = ffma2(a01.x, bs, acc[0][m]);
                    acc[1][m] = ffma2(a01.y, bs, acc[1][m]);
                    acc[2][m] = ffma2(a23.x, bs, acc[2][m]);
                    acc[3][m] = ffma2(a23.y, bs, acc[3][m]);
                }
            }
            if (kb < 31) {
                STS_STAGE(cur ^ 1);
                if (kb < 30) LDG_STAGE((kb + 2) * 16);
                __syncthreads();
            }
        }

        // epilogue: dist = (rownorm - 2*dot) + knorm, running argmin
        #pragma unroll
        for (int m = 0; m < 8; m++) {
            const int col = cBase + tx + 16 * m;
            const float kn = g_knorm[col];
            #pragma unroll
            for (int r = 0; r < 4; r++) {
                float2 d = unpack2(acc[r][m]);
                float d0 = __fadd_rn(__fadd_rn(rn[2 * r],     -__fmul_rn(2.0f, d.x)), kn);
                float d1 = __fadd_rn(__fadd_rn(rn[2 * r + 1], -__fmul_rn(2.0f, d.y)), kn);
                if (d0 < best[2 * r])     { best[2 * r]     = d0; bidx[2 * r]     = col; }
                if (d1 < best[2 * r + 1]) { best[2 * r + 1] = d1; bidx[2 * r + 1] = col; }
            }
        }
        __syncthreads();   // protect smem before next ct's prologue STS
        #undef LDG_STAGE
        #undef STS_STAGE
    }

    // cross-thread reduction over the 16 tx groups, then global combine
    #pragma unroll
    for (int r = 0; r < 8; r++) {
        sm.r.sD[ty * 8 + r][tx] = best[r];
        sm.r.sI[ty * 8 + r][tx] = bidx[r];
    }
    __syncthreads();
    if (tid < 128) {
        float bv = sm.r.sD[tid][0];
        int   bi = sm.r.sI[tid][0];
        #pragma unroll
        for (int j = 1; j < 16; j++) {
            float v  = sm.r.sD[tid][j];
            int   ii = sm.r.sI[tid][j];
            if (v < bv || (v == bv && ii < bi)) { bv = v; bi = ii; }
        }
        unsigned long long key = ((unsigned long long)fmono(bv) << 32) | (unsigned)bi;
        atomicMin(&g_best[rBase + tid], key);
    }
}

// ================= kernel 3b: finalize argmin (x_l + fit) ==================
__global__ void vq_argmin_final_kernel(float* __restrict__ out_xl) {
    const int i = blockIdx.x * 256 + threadIdx.x;
    unsigned long long key = g_best[i];
    int idx = (int)(unsigned)(key & 0xFFFFFFFFull);
    float dist = fmono_inv((unsigned)(key >> 32));
    g_xl[i] = idx;
    out_xl[i] = (float)idx;
    double s = warp_sum_d((double)dist);
    if ((threadIdx.x & 31) == 0) atomicAdd(&g_red[2], s);   // fit sum
}

// ================= kernel 4: x_d[n,w,t] = k[x_l[n*T+t], w] =================
__global__ void vq_xd_kernel(const float* __restrict__ kmat, float* __restrict__ out_xd) {
    __shared__ int   sj[32];
    __shared__ float kk[32][33];
    const int n  = blockIdx.z;
    const int w0 = blockIdx.y * 32;
    const int t0 = blockIdx.x * 32;
    const int tx = threadIdx.x;
    const int ty = threadIdx.y;
    if (ty == 0) sj[tx] = g_xl[n * TB + t0 + tx];
    __syncthreads();
    kk[ty][tx] = kmat[(size_t)sj[ty] * WDIM + w0 + tx];
    __syncthreads();
    out_xd[((size_t)n * WDIM + w0 + ty) * TB + t0 + tx] = kk[tx][ty];
}

// ================= kernel 5: scatter cluster stats + commit loss ============
__global__ void vq_scatter_kernel(const float* __restrict__ kmat) {
    const int lane = threadIdx.x & 31;
    const int warp = threadIdx.x >> 5;
    const int row  = blockIdx.x * 8 + warp;
    if (row >= NT) return;
    const int j = g_xl[row];
    const float* xr = g_xf + (size_t)row * WDIM;
    const float* kr = kmat + (size_t)j * WDIM;
    float c = 0.0f;
    for (int w = lane; w < WDIM; w += 32) {
        float xv = xr[w];
        atomicAdd(&g_ksum_acc[(size_t)j * WDIM + w], xv);
        float d = xv - kr[w];
        c += d * d;
    }
    c = warp_sum(c);
    if (lane == 0) {
        atomicAdd(&g_red[3], (double)c);
        atomicAdd(&g_kelem_acc[j], 1.0f);
    }
}

// ================= kernel 6: EMA update, k_new, dk =================
__global__ void vq_knew_kernel(const float* __restrict__ kmat,
                               const float* __restrict__ ksum_in,
                               const float* __restrict__ kelem_in,
                               float* __restrict__ out_knew,
                               float* __restrict__ out_ksumnew,
                               float* __restrict__ out_kelemnew) {
    __shared__ float s_en;
    __shared__ float sred[4];
    const int j = blockIdx.x;
    const int tid = threadIdx.x;  // 128
    if (tid == 0) {
        float en = __fadd_rn(__fmul_rn(MU_F, kelem_in[j]), __fmul_rn(OMM_F, g_kelem_acc[j]));
        s_en = en;
        out_kelemnew[j] = en;
    }
    __syncthreads();
    const float en = s_en;
    const bool usage = (en >= 1.0f);   // THRESHOLD=1.0
    const float* krand_row = g_xf + (size_t)g_ind[j] * WDIM;
    float dks = 0.0f;
    for (int w = tid; w < WDIM; w += 128) {
        size_t idx = (size_t)j * WDIM + w;
        float ksn = __fadd_rn(__fmul_rn(MU_F, ksum_in[idx]), __fmul_rn(OMM_F, g_ksum_acc[idx]));
        out_ksumnew[idx] = ksn;
        float kn = usage ? __fdiv_rn(ksn, en) : krand_row[w];
        out_knew[idx] = kn;
        float d = kn - kmat[idx];
        dks += d * d;
    }
    dks = warp_sum(dks);
    if ((tid & 31) == 0) sred[tid >> 5] = dks;
    __syncthreads();
    if (tid == 0) {
        float t = sred[0] + sred[1] + sred[2] + sred[3];
        atomicAdd(&g_red[4], (double)t);
    }
}

// ================= kernel 7: scalars =================
__global__ void vq_final_kernel(float* __restrict__ o_scal) {
    __shared__ double sE[8];
    const int tid = threadIdx.x;   // 256
    double le = 0.0;
    for (int j = tid; j < KC; j += 256) {
        float cnt = g_kelem_acc[j];
        float p = __fdiv_rn(cnt, 16384.0f);
        le += (double)(p * logf(__fadd_rn(p, 1e-8f)));
    }
    le = warp_sum_d(le);
    if ((tid & 31) == 0) sE[tid >> 5] = le;
    __syncthreads();
    if (tid == 0) {
        double ent = 0.0;
        #pragma unroll
        for (int j = 0; j < 8; j++) ent += sE[j];
        const double SZ = (double)NT * (double)WDIM;
        double mean = g_red[0] / SZ;
        o_scal[0] = (float)(g_red[3] / SZ);                    // commit_loss
        o_scal[1] = (float)(g_red[2] / (double)NT);            // fit
        o_scal[2] = (float)sqrt(g_red[1] / SZ - mean * mean);  // prenorm
        o_scal[3] = (float)(-ent);                             // entropy
        o_scal[4] = (float)(sqrt(g_red[4]) / 1024.0);          // dk
    }
}

// ================= launch =================
extern "C" void kernel_launch(void* const* d_in, const int* in_sizes, int n_in,
                              void* d_out, int out_size) {
    (void)in_sizes; (void)n_in; (void)out_size;
    const float* x     = (const float*)d_in[0];   // [16,512,1024]
    const float* k     = (const float*)d_in[1];   // [2048,512]
    const float* ksum  = (const float*)d_in[2];   // [2048,512]
    const float* kelem = (const float*)d_in[3];   // [2048]
    float* out = (float*)d_out;

    vq_zero_kernel<<<1024, 256>>>();
    vq_rng_kernel<<<NT / 256, 256>>>();
    vq_rank_partial_kernel<<<dim3(64, 8, 2), 256>>>();
    vq_perm_scatter1_kernel<<<NT / 256, 256>>>();
    vq_perm_scatter2_kernel<<<NT / 256, 256>>>();
    vq_transpose_kernel<<<dim3(TB / 32, WDIM / 32, NB), dim3(32, 8)>>>(x);
    vq_knorm_kernel<<<KC / 4, 128>>>(k);
    vq_argmin_kernel<<<dim3(NT / 128, 2), 256>>>(k);
    vq_argmin_final_kernel<<<NT / 256, 256>>>(out + O_XL);
    vq_xd_kernel<<<dim3(TB / 32, WDIM / 32, NB), dim3(32, 32)>>>(k, out + O_XD);
    vq_scatter_kernel<<<NT / 8, 256>>>(k);
    vq_knew_kernel<<<KC, 128>>>(k, ksum, kelem,
                                out + O_KNEW, out + O_KSUM, out + O_KELEM);
    vq_final_kernel<<<1, 256>>>(out + O_SCAL);
}

// round 8
// speedup vs baseline: 2.5854x; 1.6736x over previous
#include <cuda_runtime.h>
#include <math.h>

// Problem dims (fixed by the reference)
#define NT    16384          // N*T rows
#define WDIM  512            // feature dim
#define KC    2048           // codebook size
#define NB    16             // N
#define TB    1024           // T

#define MU_F   0.99f
#define OMM_F  ((float)(1.0 - 0.99))   // exact JAX constant
#define EPSM   0.125f                  // candidate margin >> tf32 dist error bound (~0.026)

// Output layout (tuple flattened, float32)
#define O_XL     0
#define O_XD     16384
#define O_SCAL   8404992
#define O_KNEW   8404997
#define O_KSUM   9453573
#define O_KELEM  10502149

// -------- scratch (static device globals) --------
__device__ float  g_xf[(size_t)NT * WDIM];
__device__ float  g_rownorm[NT];
__device__ float  g_knorm[KC];
__device__ int    g_xl[NT];
__device__ float  g_dist[(size_t)NT * KC];       // 128 MiB approx dist (kn - 2*dot)
__device__ float  g_ksum_acc[(size_t)KC * WDIM];
__device__ float  g_kelem_acc[KC];
__device__ double g_red[8];                      // 0 sum, 1 sumsq, 2 fit, 3 commit, 4 dk
// permutation machinery (jax.random.permutation(key(42), xf) reproduction)
__device__ unsigned int g_sk1[NT];
__device__ unsigned int g_sk2[NT];
__device__ int    g_rank1[NT];
__device__ int    g_rank2[NT];
__device__ int    g_v1[NT];
__device__ int    g_ind[NT];

// -------- helpers --------
__device__ __forceinline__ float warp_sum(float v) {
    #pragma unroll
    for (int o = 16; o > 0; o >>= 1) v += __shfl_xor_sync(0xffffffffu, v, o);
    return v;
}
__device__ __forceinline__ double warp_sum_d(double v) {
    #pragma unroll
    for (int o = 16; o > 0; o >>= 1) v += __shfl_xor_sync(0xffffffffu, v, o);
    return v;
}

// monotone float->uint map (order-preserving for all finite floats)
__device__ __forceinline__ unsigned int fmono(float f) {
    unsigned int b = __float_as_uint(f);
    return (b & 0x80000000u) ? ~b : (b | 0x80000000u);
}
__device__ __forceinline__ float fmono_inv(unsigned int u) {
    unsigned int b = (u & 0x80000000u) ? (u & 0x7FFFFFFFu) : ~u;
    return __uint_as_float(b);
}

// fp32 -> tf32 (round-to-nearest), result in b32 reg
__device__ __forceinline__ unsigned int f2tf32(float f) {
    unsigned int u;
    asm("cvt.rna.tf32.f32 %0, %1;" : "=r"(u) : "f"(f));
    return u;
}

// m16n8k8 tf32 mma, D += A*B
__device__ __forceinline__ void mma_tf32(float* d, const unsigned int* a,
                                         unsigned int b0, unsigned int b1) {
    asm volatile(
        "mma.sync.aligned.m16n8k8.row.col.f32.tf32.tf32.f32 "
        "{%0,%1,%2,%3}, {%4,%5,%6,%7}, {%8,%9}, {%0,%1,%2,%3};"
        : "+f"(d[0]), "+f"(d[1]), "+f"(d[2]), "+f"(d[3])
        : "r"(a[0]), "r"(a[1]), "r"(a[2]), "r"(a[3]), "r"(b0), "r"(b1));
}

// -------- Threefry-2x32 (exact JAX cipher) --------
#define TF_ROUND(x0, x1, r) { x0 += x1; x1 = ((x1) << (r)) | ((x1) >> (32 - (r))); x1 ^= x0; }

__device__ __forceinline__ uint2 threefry2x32(unsigned int k0, unsigned int k1,
                                              unsigned int x0, unsigned int x1) {
    unsigned int k2 = k0 ^ k1 ^ 0x1BD11BDAu;
    x0 += k0; x1 += k1;
    TF_ROUND(x0, x1, 13) TF_ROUND(x0, x1, 15) TF_ROUND(x0, x1, 26) TF_ROUND(x0, x1, 6)
    x0 += k1; x1 += k2 + 1u;
    TF_ROUND(x0, x1, 17) TF_ROUND(x0, x1, 29) TF_ROUND(x0, x1, 16) TF_ROUND(x0, x1, 24)
    x0 += k2; x1 += k0 + 2u;
    TF_ROUND(x0, x1, 13) TF_ROUND(x0, x1, 15) TF_ROUND(x0, x1, 26) TF_ROUND(x0, x1, 6)
    x0 += k0; x1 += k1 + 3u;
    TF_ROUND(x0, x1, 17) TF_ROUND(x0, x1, 29) TF_ROUND(x0, x1, 16) TF_ROUND(x0, x1, 24)
    x0 += k1; x1 += k2 + 4u;
    TF_ROUND(x0, x1, 13) TF_ROUND(x0, x1, 15) TF_ROUND(x0, x1, 26) TF_ROUND(x0, x1, 6)
    x0 += k2; x1 += k0 + 5u;
    return make_uint2(x0, x1);
}

// ================= kernel 0: zero scratch =================
__global__ void vq_zero_kernel() {
    int i = blockIdx.x * blockDim.x + threadIdx.x;
    int stride = gridDim.x * blockDim.x;
    for (int idx = i; idx < KC * WDIM; idx += stride) g_ksum_acc[idx] = 0.0f;
    for (int idx = i; idx < KC;        idx += stride) g_kelem_acc[idx] = 0.0f;
    for (int idx = i; idx < NT;        idx += stride) {
        g_rownorm[idx] = 0.0f;
        g_rank1[idx] = 0;
        g_rank2[idx] = 0;
    }
    if (i < 8) g_red[i] = 0.0;
}

// ================= kernel R0: sort keys, threefry_partitionable semantics ======
__global__ void vq_rng_kernel() {
    const int i = blockIdx.x * blockDim.x + threadIdx.x;   // 0..16383
    if (i >= NT) return;
    uint2 k1 = threefry2x32(0u, 42u, 0u, 0u);    // round-1 carried key
    uint2 s1 = threefry2x32(0u, 42u, 0u, 1u);    // round-1 subkey
    uint2 s2 = threefry2x32(k1.x, k1.y, 0u, 1u); // round-2 subkey

    uint2 r1 = threefry2x32(s1.x, s1.y, 0u, (unsigned)i);
    g_sk1[i] = r1.x ^ r1.y;
    uint2 r2 = threefry2x32(s2.x, s2.y, 0u, (unsigned)i);
    g_sk2[i] = r2.x ^ r2.y;
}

// ================= kernel R1: partial stable-sort ranks (full-chip) =========
__global__ void vq_rank_partial_kernel() {
    __shared__ unsigned long long s[2048];
    const unsigned int* sk = (blockIdx.z == 0) ? g_sk1 : g_sk2;
    int* grank             = (blockIdx.z == 0) ? g_rank1 : g_rank2;
    const int i  = blockIdx.x * 256 + threadIdx.x;
    const int c0 = blockIdx.y * 2048;
    for (int j = threadIdx.x; j < 2048; j += 256)
        s[j] = ((unsigned long long)sk[c0 + j] << 32) | (unsigned)(c0 + j);
    __syncthreads();
    const unsigned long long ci = ((unsigned long long)sk[i] << 32) | (unsigned)i;
    int cnt = 0;
    #pragma unroll 16
    for (int j = 0; j < 2048; j++) cnt += (s[j] < ci) ? 1 : 0;
    atomicAdd(&grank[i], cnt);
}

__global__ void vq_perm_scatter1_kernel() {
    const int i = blockIdx.x * 256 + threadIdx.x;
    g_v1[g_rank1[i]] = i;              // round-1: sorted_val[rank] = i
}
__global__ void vq_perm_scatter2_kernel() {
    const int i = blockIdx.x * 256 + threadIdx.x;
    g_ind[g_rank2[i]] = g_v1[i];       // round-2: k_rand[j] = xf[g_ind[j]]
}

// ================= kernel 1: transpose x[N,W,T] -> xf[NT,W] + stats =========
__global__ void vq_transpose_kernel(const float* __restrict__ x) {
    __shared__ float tile[32][33];
    __shared__ float sWs[8], sWq[8];
    const int n  = blockIdx.z;
    const int w0 = blockIdx.y * 32;
    const int t0 = blockIdx.x * 32;
    const int tx = threadIdx.x;   // 32
    const int ty = threadIdx.y;   // 8

    float ls = 0.0f, lq = 0.0f;
    #pragma unroll
    for (int i = 0; i < 4; i++) {
        int wl = ty + i * 8;
        float v = x[((size_t)n * WDIM + (w0 + wl)) * TB + t0 + tx];
        tile[wl][tx] = v;
        ls += v;
        lq += v * v;
    }
    __syncthreads();
    #pragma unroll
    for (int i = 0; i < 4; i++) {
        int tl = ty + i * 8;
        float v = tile[tx][tl];                      // w = w0+tx, t = t0+tl
        g_xf[((size_t)(n * TB + t0 + tl)) * WDIM + w0 + tx] = v;
        float s = warp_sum(v * v);
        if (tx == 0) atomicAdd(&g_rownorm[n * TB + t0 + tl], s);
    }
    ls = warp_sum(ls);
    lq = warp_sum(lq);
    if (tx == 0) { sWs[ty] = ls; sWq[ty] = lq; }
    __syncthreads();
    if (tx == 0 && ty == 0) {
        float a = 0.0f, b = 0.0f;
        #pragma unroll
        for (int j = 0; j < 8; j++) { a += sWs[j]; b += sWq[j]; }
        atomicAdd(&g_red[0], (double)a);
        atomicAdd(&g_red[1], (double)b);
    }
}

// ================= kernel 2: codebook row norms =================
__global__ void vq_knorm_kernel(const float* __restrict__ kmat) {
    const int lane = threadIdx.x & 31;
    const int warp = threadIdx.x >> 5;
    const int c = blockIdx.x * 4 + warp;
    if (c >= KC) return;
    float s = 0.0f;
    for (int w = lane; w < WDIM; w += 32) {
        float v = kmat[(size_t)c * WDIM + w];
        s += v * v;
    }
    s = warp_sum(s);
    if (lane == 0) g_knorm[c] = s;
}

// ================= kernel 3a: tf32 tensor-core dist GEMM ====================
// grid (NT/128, 2): 128-row block x 1024-code half; block loops 8 tiles of 128.
// Block 256 thr = 8 warps (4 m x 2 n); warp tile 32x64 via m16n8k8 tf32 mma.
// Writes approx dist' = kn - 2*dot (rn omitted: constant per row, doesn't
// affect argmin or margins). Stride-20 smem padding -> conflict-free frag LDS.
__global__ void __launch_bounds__(256, 2) vq_dist_kernel(const float* __restrict__ kmat) {
    __shared__ unsigned int As[2][128][20];
    __shared__ unsigned int Bs[2][128][20];

    const int tid  = threadIdx.x;
    const int lane = tid & 31;
    const int wid  = tid >> 5;           // 0..7
    const int warp_m = wid & 3;          // m offset = 32*warp_m
    const int warp_n = wid >> 2;         // n offset = 64*warp_n
    const int g   = lane >> 2;           // 0..7
    const int tig = lane & 3;            // 0..3
    const int rBase  = blockIdx.x * 128;
    const int cBase0 = blockIdx.y * 1024;

    const int srow = tid >> 1;           // staging row 0..127
    const int sk   = (tid & 1) * 8;      // staging k half
    const float* Arow = g_xf + (size_t)(rBase + srow) * WDIM + sk;

    for (int ct = 0; ct < 8; ct++) {
        const int cBase = cBase0 + ct * 128;
        const float* Brow = kmat + (size_t)(cBase + srow) * WDIM + sk;

        float acc[2][8][4];
        #pragma unroll
        for (int mi = 0; mi < 2; mi++)
            #pragma unroll
            for (int ni = 0; ni < 8; ni++)
                #pragma unroll
                for (int q = 0; q < 4; q++) acc[mi][ni][q] = 0.0f;

        float4 a4a, a4b, b4a, b4b;

        #define LDG_ST(wb) {                                    \
            a4a = *(const float4*)(Arow + (wb));                \
            a4b = *(const float4*)(Arow + (wb) + 4);            \
            b4a = *(const float4*)(Brow + (wb));                \
            b4b = *(const float4*)(Brow + (wb) + 4);            \
        }
        #define STS_ST(buf) {                                   \
            As[buf][srow][sk + 0] = f2tf32(a4a.x);              \
            As[buf][srow][sk + 1] = f2tf32(a4a.y);              \
            As[buf][srow][sk + 2] = f2tf32(a4a.z);              \
            As[buf][srow][sk + 3] = f2tf32(a4a.w);              \
            As[buf][srow][sk + 4] = f2tf32(a4b.x);              \
            As[buf][srow][sk + 5] = f2tf32(a4b.y);              \
            As[buf][srow][sk + 6] = f2tf32(a4b.z);              \
            As[buf][srow][sk + 7] = f2tf32(a4b.w);              \
            Bs[buf][srow][sk + 0] = f2tf32(b4a.x);              \
            Bs[buf][srow][sk + 1] = f2tf32(b4a.y);              \
            Bs[buf][srow][sk + 2] = f2tf32(b4a.z);              \
            Bs[buf][srow][sk + 3] = f2tf32(b4a.w);              \
            Bs[buf][srow][sk + 4] = f2tf32(b4b.x);              \
            Bs[buf][srow][sk + 5] = f2tf32(b4b.y);              \
            Bs[buf][srow][sk + 6] = f2tf32(b4b.z);              \
            Bs[buf][srow][sk + 7] = f2tf32(b4b.w);              \
        }

        LDG_ST(0);
        STS_ST(0);
        LDG_ST(16);
        __syncthreads();

        #pragma unroll 1
        for (int kb = 0; kb < 32; kb++) {
            const int cur = kb & 1;
            #pragma unroll
            for (int koi = 0; koi < 2; koi++) {
                const int ko = koi * 8;
                unsigned int af[2][4];
                #pragma unroll
                for (int mi = 0; mi < 2; mi++) {
                    const int rb = warp_m * 32 + mi * 16;
                    af[mi][0] = As[cur][rb + g    ][ko + tig];
                    af[mi][1] = As[cur][rb + g + 8][ko + tig];
                    af[mi][2] = As[cur][rb + g    ][ko + tig + 4];
                    af[mi][3] = As[cur][rb + g + 8][ko + tig + 4];
                }
                #pragma unroll
                for (int ni = 0; ni < 8; ni++) {
                    const int cb = warp_n * 64 + ni * 8;
                    unsigned int b0 = Bs[cur][cb + g][ko + tig];
                    unsigned int b1 = Bs[cur][cb + g][ko + tig + 4];
                    mma_tf32(acc[0][ni], af[0], b0, b1);
                    mma_tf32(acc[1][ni], af[1], b0, b1);
                }
            }
            if (kb < 31) {
                STS_ST(cur ^ 1);
                if (kb < 30) LDG_ST((kb + 2) * 16);
                __syncthreads();
            }
        }

        // epilogue: approx dist' = kn - 2*dot
        #pragma unroll
        for (int mi = 0; mi < 2; mi++) {
            #pragma unroll
            for (int ni = 0; ni < 8; ni++) {
                const int row0 = rBase + warp_m * 32 + mi * 16 + g;
                const int col0 = cBase + warp_n * 64 + ni * 8 + tig * 2;
                const float2 kn = *(const float2*)&g_knorm[col0];
                float2 o0, o1;
                o0.x = fmaf(-2.0f, acc[mi][ni][0], kn.x);
                o0.y = fmaf(-2.0f, acc[mi][ni][1], kn.y);
                o1.x = fmaf(-2.0f, acc[mi][ni][2], kn.x);
                o1.y = fmaf(-2.0f, acc[mi][ni][3], kn.y);
                *(float2*)(g_dist + (size_t)row0 * KC + col0)       = o0;
                *(float2*)(g_dist + (size_t)(row0 + 8) * KC + col0) = o1;
            }
        }
        __syncthreads();   // protect smem before next ct's prologue STS
        #undef LDG_ST
        #undef STS_ST
    }
}

// ================= kernel 3b: candidate scan + exact fp32 rescore ===========
// One warp per row. Approx min over 2048 dists, then rescore every candidate
// within EPSM exactly (sequential-w fp32 fmaf + identical epilogue ops) ->
// bit-identical decisions to the reference-matched FFMA2 kernel.
__global__ void __launch_bounds__(256) vq_select_kernel(const float* __restrict__ kmat,
                                                        float* __restrict__ out_xl) {
    __shared__ float  sx[8][512];
    __shared__ double sfit[8];
    const int lane = threadIdx.x & 31;
    const int warp = threadIdx.x >> 5;
    const int row  = blockIdx.x * 8 + warp;

    // stage x row into smem
    const float4* xr4 = (const float4*)(g_xf + (size_t)row * WDIM);
    float4* sx4 = (float4*)sx[warp];
    #pragma unroll
    for (int j = lane; j < 128; j += 32) sx4[j] = xr4[j];
    __syncwarp();

    const float rn = g_rownorm[row];
    const float4* dr4 = (const float4*)(g_dist + (size_t)row * KC);

    // pass A: approximate min (value only matters up to EPSM)
    float bm = __int_as_float(0x7f800000);
    int   bi = 0;
    #pragma unroll
    for (int j = 0; j < 16; j++) {
        float4 v = dr4[j * 32 + lane];
        int base = j * 128 + lane * 4;
        if (v.x < bm) { bm = v.x; bi = base; }
        if (v.y < bm) { bm = v.y; bi = base + 1; }
        if (v.z < bm) { bm = v.z; bi = base + 2; }
        if (v.w < bm) { bm = v.w; bi = base + 3; }
    }
    unsigned long long key = ((unsigned long long)fmono(bm) << 32) | (unsigned)bi;
    #pragma unroll
    for (int o = 16; o > 0; o >>= 1) {
        unsigned long long other = __shfl_xor_sync(0xffffffffu, key, o);
        if (other < key) key = other;
    }
    const float thr = fmono_inv((unsigned)(key >> 32)) + EPSM;

    // pass B: exact rescore of candidates
    unsigned long long bkey = 0xFFFFFFFFFFFFFFFFull;
    #pragma unroll 1
    for (int j = 0; j < 16; j++) {
        float4 v = dr4[j * 32 + lane];
        const int base = j * 128 + lane * 4;
        #pragma unroll
        for (int c = 0; c < 4; c++) {
            float dv = (c == 0) ? v.x : (c == 1) ? v.y : (c == 2) ? v.z : v.w;
            if (dv <= thr) {
                const int idx = base + c;
                const float4* kr4 = (const float4*)(kmat + (size_t)idx * WDIM);
                float acc = 0.0f;
                #pragma unroll 4
                for (int w = 0; w < 128; w++) {
                    float4 xv = sx4[w];
                    float4 kv = kr4[w];
                    acc = fmaf(xv.x, kv.x, acc);
                    acc = fmaf(xv.y, kv.y, acc);
                    acc = fmaf(xv.z, kv.z, acc);
                    acc = fmaf(xv.w, kv.w, acc);
                }
                float dist = __fadd_rn(__fadd_rn(rn, -__fmul_rn(2.0f, acc)), g_knorm[idx]);
                unsigned long long k2 =
                    ((unsigned long long)fmono(dist) << 32) | (unsigned)idx;
                if (k2 < bkey) bkey = k2;
            }
        }
    }
    #pragma unroll
    for (int o = 16; o > 0; o >>= 1) {
        unsigned long long other = __shfl_xor_sync(0xffffffffu, bkey, o);
        if (other < bkey) bkey = other;
    }
    if (lane == 0) {
        const int idx = (int)(unsigned)(bkey & 0xFFFFFFFFull);
        const float dist = fmono_inv((unsigned)(bkey >> 32));
        g_xl[row] = idx;
        out_xl[row] = (float)idx;
        sfit[warp] = (double)dist;
    }
    __syncthreads();
    if (threadIdx.x == 0) {
        double s = 0.0;
        #pragma unroll
        for (int j = 0; j < 8; j++) s += sfit[j];
        atomicAdd(&g_red[2], s);   // fit sum
    }
}

// ================= kernel 4: x_d[n,w,t] = k[x_l[n*T+t], w] =================
__global__ void vq_xd_kernel(const float* __restrict__ kmat, float* __restrict__ out_xd) {
    __shared__ int   sj[32];
    __shared__ float kk[32][33];
    const int n  = blockIdx.z;
    const int w0 = blockIdx.y * 32;
    const int t0 = blockIdx.x * 32;
    const int tx = threadIdx.x;
    const int ty = threadIdx.y;
    if (ty == 0) sj[tx] = g_xl[n * TB + t0 + tx];
    __syncthreads();
    kk[ty][tx] = kmat[(size_t)sj[ty] * WDIM + w0 + tx];
    __syncthreads();
    out_xd[((size_t)n * WDIM + w0 + ty) * TB + t0 + tx] = kk[tx][ty];
}

// ================= kernel 5: scatter cluster stats + commit loss ============
__global__ void vq_scatter_kernel(const float* __restrict__ kmat) {
    const int lane = threadIdx.x & 31;
    const int warp = threadIdx.x >> 5;
    const int row  = blockIdx.x * 8 + warp;
    if (row >= NT) return;
    const int j = g_xl[row];
    const float* xr = g_xf + (size_t)row * WDIM;
    const float* kr = kmat + (size_t)j * WDIM;
    float c = 0.0f;
    for (int w = lane; w < WDIM; w += 32) {
        float xv = xr[w];
        atomicAdd(&g_ksum_acc[(size_t)j * WDIM + w], xv);
        float d = xv - kr[w];
        c += d * d;
    }
    c = warp_sum(c);
    if (lane == 0) {
        atomicAdd(&g_red[3], (double)c);
        atomicAdd(&g_kelem_acc[j], 1.0f);
    }
}

// ================= kernel 6: EMA update, k_new, dk =================
__global__ void vq_knew_kernel(const float* __restrict__ kmat,
                               const float* __restrict__ ksum_in,
                               const float* __restrict__ kelem_in,
                               float* __restrict__ out_knew,
                               float* __restrict__ out_ksumnew,
                               float* __restrict__ out_kelemnew) {
    __shared__ float s_en;
    __shared__ float sred[4];
    const int j = blockIdx.x;
    const int tid = threadIdx.x;  // 128
    if (tid == 0) {
        float en = __fadd_rn(__fmul_rn(MU_F, kelem_in[j]), __fmul_rn(OMM_F, g_kelem_acc[j]));
        s_en = en;
        out_kelemnew[j] = en;
    }
    __syncthreads();
    const float en = s_en;
    const bool usage = (en >= 1.0f);   // THRESHOLD=1.0
    const float* krand_row = g_xf + (size_t)g_ind[j] * WDIM;
    float dks = 0.0f;
    for (int w = tid; w < WDIM; w += 128) {
        size_t idx = (size_t)j * WDIM + w;
        float ksn = __fadd_rn(__fmul_rn(MU_F, ksum_in[idx]), __fmul_rn(OMM_F, g_ksum_acc[idx]));
        out_ksumnew[idx] = ksn;
        float kn = usage ? __fdiv_rn(ksn, en) : krand_row[w];
        out_knew[idx] = kn;
        float d = kn - kmat[idx];
        dks += d * d;
    }
    dks = warp_sum(dks);
    if ((tid & 31) == 0) sred[tid >> 5] = dks;
    __syncthreads();
    if (tid == 0) {
        float t = sred[0] + sred[1] + sred[2] + sred[3];
        atomicAdd(&g_red[4], (double)t);
    }
}

// ================= kernel 7: scalars =================
__global__ void vq_final_kernel(float* __restrict__ o_scal) {
    __shared__ double sE[8];
    const int tid = threadIdx.x;   // 256
    double le = 0.0;
    for (int j = tid; j < KC; j += 256) {
        float cnt = g_kelem_acc[j];
        float p = __fdiv_rn(cnt, 16384.0f);
        le += (double)(p * logf(__fadd_rn(p, 1e-8f)));
    }
    le = warp_sum_d(le);
    if ((tid & 31) == 0) sE[tid >> 5] = le;
    __syncthreads();
    if (tid == 0) {
        double ent = 0.0;
        #pragma unroll
        for (int j = 0; j < 8; j++) ent += sE[j];
        const double SZ = (double)NT * (double)WDIM;
        double mean = g_red[0] / SZ;
        o_scal[0] = (float)(g_red[3] / SZ);                    // commit_loss
        o_scal[1] = (float)(g_red[2] / (double)NT);            // fit
        o_scal[2] = (float)sqrt(g_red[1] / SZ - mean * mean);  // prenorm
        o_scal[3] = (float)(-ent);                             // entropy
        o_scal[4] = (float)(sqrt(g_red[4]) / 1024.0);          // dk
    }
}

// ================= launch =================
extern "C" void kernel_launch(void* const* d_in, const int* in_sizes, int n_in,
                              void* d_out, int out_size) {
    (void)in_sizes; (void)n_in; (void)out_size;
    const float* x     = (const float*)d_in[0];   // [16,512,1024]
    const float* k     = (const float*)d_in[1];   // [2048,512]
    const float* ksum  = (const float*)d_in[2];   // [2048,512]
    const float* kelem = (const float*)d_in[3];   // [2048]
    float* out = (float*)d_out;

    vq_zero_kernel<<<1024, 256>>>();
    vq_rng_kernel<<<NT / 256, 256>>>();
    vq_rank_partial_kernel<<<dim3(64, 8, 2), 256>>>();
    vq_perm_scatter1_kernel<<<NT / 256, 256>>>();
    vq_perm_scatter2_kernel<<<NT / 256, 256>>>();
    vq_transpose_kernel<<<dim3(TB / 32, WDIM / 32, NB), dim3(32, 8)>>>(x);
    vq_knorm_kernel<<<KC / 4, 128>>>(k);
    vq_dist_kernel<<<dim3(NT / 128, 2), 256>>>(k);
    vq_select_kernel<<<NT / 8, 256>>>(k, out + O_XL);
    vq_xd_kernel<<<dim3(TB / 32, WDIM / 32, NB), dim3(32, 32)>>>(k, out + O_XD);
    vq_scatter_kernel<<<NT / 8, 256>>>(k);
    vq_knew_kernel<<<KC, 128>>>(k, ksum, kelem,
                                out + O_KNEW, out + O_KSUM, out + O_KELEM);
    vq_final_kernel<<<1, 256>>>(out + O_SCAL);
}